// round 16
// baseline (speedup 1.0000x reference)
#include <cuda_runtime.h>

// Problem constants
#define BS   64
#define SEQ  512
#define H    768
#define TT   64   // topic count per batch
#define KK   64   // token count per batch

#define RPB      8            // rows per block in rows_kernel
#define RTHREADS 256
#define ROW_BYTES (H * 4)     // 3072

// g_A[b][m][p]: m in {cls_c0, cls_c1, topic_c0, topic_c1, token_c0, token_c1}
__device__ float4 g_A4[BS * 6 * H / 4];

// rows_kernel dynamic smem: sA[2*768] + sH[8*768] floats = 30720 B
#define RSMEM_BYTES ((2 * H + RPB * H) * 4)

// ---------------------------------------------------------------------------
// Kernel 1: build the 6 factored A vectors per batch — smem-staged W.
// ---------------------------------------------------------------------------
__global__ void __launch_bounds__(256) build_A_kernel(
    const float* __restrict__ Wsrc,   // [862, 384]
    const float* __restrict__ Wtgt,   // [862, 384]
    const float* __restrict__ Wcls,   // [2, 6144]
    const float* __restrict__ Wtopic, // [2, 6144]
    const float* __restrict__ Wtoken, // [2, 6144]
    const int*   __restrict__ src_ids,
    const int*   __restrict__ tgt_ids)
{
    const int b   = blockIdx.x;
    const int m   = blockIdx.y;      // 0..5
    const int tid = threadIdx.x;

    __shared__ float sW[6144];       // 24 KB
    __shared__ float d0[H];          // 3 KB

    const int w = m >> 1;
    const int c = m & 1;
    const float4* __restrict__ Wb = (const float4*)(
        (w == 0 ? Wcls : (w == 1 ? Wtopic : Wtoken)) + c * 6144);

    {
        float4* sW4 = (float4*)sW;
#pragma unroll
        for (int e = tid; e < 1536; e += 256)
            sW4[e] = Wb[e];

        const float4* __restrict__ s =
            (const float4*)(Wsrc + (size_t)src_ids[b] * 384);
        const float4* __restrict__ t =
            (const float4*)(Wtgt + (size_t)tgt_ids[b] * 384);
        float4* d04 = (float4*)d0;
        if (tid < 96)       d04[tid]           = s[tid];
        else if (tid < 192) d04[tid - 96 + 96] = t[tid - 96];
    }
    __syncthreads();

    float* __restrict__ Ab = ((float*)g_A4) + ((size_t)b * 6 + m) * H;

#pragma unroll
    for (int e = tid; e < H; e += 256) {
        const int g = e >> 3;
        const int j = e & 7;
        const float* __restrict__ Wp = sW + g * 64 + j;
        const float* __restrict__ d  = d0 + g * 8;
        float acc = 0.f;
#pragma unroll
        for (int i = 0; i < 8; i++)
            acc = fmaf(d[i], Wp[i * 8], acc);
        Ab[e] = acc;
    }

#if __CUDA_ARCH__ >= 900
    cudaTriggerProgrammaticLaunchCompletion();
#endif
}

// ---------------------------------------------------------------------------
// Kernel 2: grid (BS, 17), 256 thr, warp-per-row, type-split blocks.
//   y in [0,7]: topic rows; y in [8,15]: token rows; y==16: cls row.
// Gather of the 3KB hidden rows now goes through the TMA engine
// (cp.async.bulk + mbarrier) to escape the per-SM L1tex outstanding-line cap.
// ---------------------------------------------------------------------------
__global__ void __launch_bounds__(RTHREADS) rows_kernel(
    const float* __restrict__ hidden,     // [BS, SEQ, H]
    const float* __restrict__ b_cls,      // [2]
    const float* __restrict__ b_topic,    // [2]
    const float* __restrict__ b_token,    // [2]
    const int*   __restrict__ topic_inds, // [BS, TT]
    const float* __restrict__ topic_mask, // [BS, TT]
    const int*   __restrict__ token_inds, // [BS, KK]
    const float* __restrict__ token_mask, // [BS, KK]
    float* __restrict__ out)              // [128 | 8192 | 8192]
{
    const int b    = blockIdx.x;
    const int y    = blockIdx.y;          // 0..16
    const int tid  = threadIdx.x;
    const int warp = tid >> 5;
    const int lane = tid & 31;

    extern __shared__ float smem[];
    float* sA = smem;           // 2*768
    float* sH = smem + 2 * H;   // 8*768
    __shared__ int   sIdx[RPB];
    __shared__ float sMask[RPB];
    __shared__ __align__(8) unsigned long long mbar;

    const unsigned mbar_u32 = (unsigned)__cvta_generic_to_shared(&mbar);
    const unsigned sH_u32   = (unsigned)__cvta_generic_to_shared(sH);

    const bool is_cls   = (y == 16);
    const bool is_topic = (y < 8);
    const int  qoff     = (y & 7) * RPB;
    const int  nrows    = is_cls ? 1 : RPB;

    // ---- Phase 1a: mbarrier init + indices + masks -----------------------
    if (tid == 0) {
        asm volatile("mbarrier.init.shared.b64 [%0], 1;"
                     :: "r"(mbar_u32) : "memory");
    }
    if (tid < nrows) {
        int idx; float mk;
        if (is_cls) {
            idx = 0; mk = 1.f;
        } else if (is_topic) {
            idx = topic_inds[b * TT + qoff + tid];
            mk  = topic_mask[b * TT + qoff + tid];
        } else {
            idx = token_inds[b * KK + qoff + tid];
            mk  = token_mask[b * KK + qoff + tid];
        }
        sIdx[tid]  = idx;
        sMask[tid] = mk;
    }
    __syncthreads();

    // ---- Phase 1b: fire the DRAM gather through the TMA engine -----------
    if (tid == 0) {
        asm volatile("mbarrier.arrive.expect_tx.shared.b64 _, [%0], %1;"
                     :: "r"(mbar_u32), "r"((unsigned)(nrows * ROW_BYTES))
                     : "memory");
#pragma unroll
        for (int rr = 0; rr < RPB; rr++) {
            if (rr < nrows) {
                const void* src = hidden + ((size_t)b * SEQ + sIdx[rr]) * H;
                asm volatile(
                    "cp.async.bulk.shared::cluster.global.mbarrier::complete_tx::bytes "
                    "[%0], [%1], %2, [%3];"
                    :: "r"(sH_u32 + (unsigned)(rr * ROW_BYTES)),
                       "l"(src), "r"((unsigned)ROW_BYTES), "r"(mbar_u32)
                    : "memory");
            }
        }
    }

    // ---- Phase 2: dependency point, then stage this block's A pair -------
#if __CUDA_ARCH__ >= 900
    cudaGridDependencySynchronize();
#endif
    {
        const int m0 = is_cls ? 0 : (is_topic ? 2 : 4);
        const float4* __restrict__ Ap = g_A4 + ((size_t)b * 6 + m0) * (H / 4);
        for (int e = tid; e < 2 * H / 4; e += RTHREADS) {
            unsigned d = (unsigned)__cvta_generic_to_shared(sA) + e * 16u;
            asm volatile("cp.async.cg.shared.global [%0], [%1], 16;\n"
                         :: "r"(d), "l"(Ap + e));
        }
    }
    asm volatile("cp.async.commit_group;\n");
    asm volatile("cp.async.wait_group 0;\n");

    // ---- Wait for the TMA gather (phase 0), then block-wide barrier ------
    {
        unsigned done;
        asm volatile(
            "{\n\t"
            ".reg .pred p;\n\t"
            "mbarrier.try_wait.parity.acquire.cta.shared::cta.b64 p, [%1], %2;\n\t"
            "selp.b32 %0, 1, 0, p;\n\t"
            "}"
            : "=r"(done) : "r"(mbar_u32), "r"(0u) : "memory");
        if (!done) {
            asm volatile(
                "{\n\t"
                ".reg .pred P1;\n\t"
                "WAIT_LOOP_%=:\n\t"
                "mbarrier.try_wait.parity.acquire.cta.shared::cta.b64 P1, [%0], %1, 0x989680;\n\t"
                "@P1 bra.uni WAIT_DONE_%=;\n\t"
                "bra.uni WAIT_LOOP_%=;\n\t"
                "WAIT_DONE_%=:\n\t"
                "}"
                :: "r"(mbar_u32), "r"(0u) : "memory");
        }
    }
    __syncthreads();   // covers other threads' sA cp.asyncs too

    // ---- Phase 3: warp-per-row dot + epilogue ----------------------------
    if (warp < nrows) {
        const float4* __restrict__ h4 = (const float4*)(sH + warp * H);
        const float4* __restrict__ a0 = (const float4*)sA;
        const float4* __restrict__ a1 = a0 + (H / 4);

        float acc0 = 0.f, acc1 = 0.f;
#pragma unroll
        for (int k = 0; k < 6; k++) {
            const int p = lane + k * 32;
            const float4 h = h4[p];
            const float4 x = a0[p];
            const float4 z = a1[p];
            acc0 = fmaf(h.x, x.x, fmaf(h.y, x.y, fmaf(h.z, x.z, fmaf(h.w, x.w, acc0))));
            acc1 = fmaf(h.x, z.x, fmaf(h.y, z.y, fmaf(h.z, z.z, fmaf(h.w, z.w, acc1))));
        }
#pragma unroll
        for (int o = 16; o; o >>= 1) {
            acc0 += __shfl_xor_sync(0xFFFFFFFFu, acc0, o);
            acc1 += __shfl_xor_sync(0xFFFFFFFFu, acc1, o);
        }

        if (lane == 0) {
            const float mask = sMask[warp];
            float bias0, bias1;
            float* outp;
            bool do_softmax;
            if (is_cls) {
                bias0 = b_cls[0]; bias1 = b_cls[1];
                outp = out + b * 2;
                do_softmax = true;
            } else if (is_topic) {
                bias0 = b_topic[0]; bias1 = b_topic[1];
                outp = out + 128 + (b * TT + qoff + warp) * 2;
                do_softmax = true;
            } else {
                bias0 = b_token[0]; bias1 = b_token[1];
                outp = out + 128 + BS * TT * 2 + (b * KK + qoff + warp) * 2;
                do_softmax = false;
            }

            const float x0 = fmaf(mask, acc0, bias0);
            const float x1 = fmaf(mask, acc1, bias1);
            if (do_softmax) {
                const float mx = fmaxf(x0, x1);
                const float e0 = __expf(x0 - mx);
                const float e1 = __expf(x1 - mx);
                const float inv = 1.f / (e0 + e1);
                outp[0] = e0 * inv;
                outp[1] = e1 * inv;
            } else {
                outp[0] = x0;
                outp[1] = x1;
            }
        }
    }
}

// ---------------------------------------------------------------------------
// Launch: fast build_A, then rows_kernel under PDL.
// ---------------------------------------------------------------------------
extern "C" void kernel_launch(void* const* d_in, const int* in_sizes, int n_in,
                              void* d_out, int out_size)
{
    const float* hidden     = (const float*)d_in[0];   // [64,512,768]
    const float* Wsrc       = (const float*)d_in[1];   // [862,384]
    const float* Wtgt       = (const float*)d_in[2];   // [862,384]
    const float* W_cls      = (const float*)d_in[3];   // [2,6144]
    const float* b_cls      = (const float*)d_in[4];   // [2]
    const float* W_topic    = (const float*)d_in[5];   // [2,6144]
    const float* b_topic    = (const float*)d_in[6];   // [2]
    const float* W_token    = (const float*)d_in[7];   // [2,6144]
    const float* b_token    = (const float*)d_in[8];   // [2]
    const int*   source_ids = (const int*)d_in[9];     // [64]
    const int*   target_ids = (const int*)d_in[10];    // [64]
    // d_in[11] ent_inds, d_in[12] ent_mask: unused by reference outputs
    const int*   topic_inds = (const int*)d_in[13];    // [64,64]
    const float* topic_mask = (const float*)d_in[14];  // [64,64]
    const int*   token_inds = (const int*)d_in[15];    // [64,64]
    const float* token_mask = (const float*)d_in[16];  // [64,64]

    float* out = (float*)d_out;

    build_A_kernel<<<dim3(BS, 6), 256>>>(Wsrc, Wtgt, W_cls, W_topic, W_token,
                                         source_ids, target_ids);

    cudaFuncSetAttribute(rows_kernel,
                         cudaFuncAttributeMaxDynamicSharedMemorySize,
                         RSMEM_BYTES);

    cudaLaunchConfig_t cfg = {};
    cfg.gridDim          = dim3(BS, 17);
    cfg.blockDim         = dim3(RTHREADS);
    cfg.dynamicSmemBytes = RSMEM_BYTES;
    cfg.stream           = 0;
    cudaLaunchAttribute attr[1];
    attr[0].id = cudaLaunchAttributeProgrammaticStreamSerialization;
    attr[0].val.programmaticStreamSerializationAllowed = 1;
    cfg.attrs    = attr;
    cfg.numAttrs = 1;

    cudaLaunchKernelEx(&cfg, rows_kernel, hidden, b_cls, b_topic, b_token,
                       topic_inds, topic_mask, token_inds, token_mask, out);
}